// round 3
// baseline (speedup 1.0000x reference)
#include <cuda_runtime.h>

#define N_ROWS 65536
#define D      64
#define NE     1024
#define CHUNK  128
#define K2_THREADS 128
#define K3_THREADS 256
#define K3_BLOCKS  (N_ROWS / K3_THREADS)   // 256
#define GAP_THRESH 1e-3f
#define REFINE_BLOCKS 128
#define REFINE_THREADS 128

// Scratch (no allocations allowed)
__device__ float g_e2[NE];
__device__ int   g_idx[N_ROWS];
__device__ float g_partial[K3_BLOCKS];
__device__ int   g_flag_cnt;
__device__ int   g_flag_rows[N_ROWS];

// ---------------------------------------------------------------------------
// Kernel 1: e2[j] = sum_d emb[j,d]^2   (+ reset flag counter)
// ---------------------------------------------------------------------------
__global__ void e2_kernel(const float* __restrict__ emb) {
    int j = blockIdx.x * blockDim.x + threadIdx.x;
    if (j == 0) g_flag_cnt = 0;
    if (j < NE) {
        const float4* e = (const float4*)(emb + (size_t)j * D);
        float s = 0.f;
        #pragma unroll
        for (int q = 0; q < 16; q++) {
            float4 v = e[q];
            s += v.x * v.x;
            s += v.y * v.y;
            s += v.z * v.z;
            s += v.w * v.w;
        }
        g_e2[j] = s;
    }
}

// ---------------------------------------------------------------------------
// Kernel 2: fast fp32 argmin (1 row/thread, codes via shared, 4-code
// register blocking). Tracks best + second-best; rows whose gap < GAP_THRESH
// are appended to a refine list (decision not trustworthy at fp32 noise).
// ---------------------------------------------------------------------------
__global__ __launch_bounds__(K2_THREADS)
void argmin_kernel(const float* __restrict__ z,
                   const float* __restrict__ emb,
                   float* __restrict__ idx_out_f) {
    __shared__ float4 sE[CHUNK * 16];
    __shared__ float  sE2[CHUNK];

    int row = blockIdx.x * K2_THREADS + threadIdx.x;

    float4 zr[16];
    const float4* zp = (const float4*)(z + (size_t)row * D);
    #pragma unroll
    for (int q = 0; q < 16; q++) zr[q] = zp[q];

    float z2 = 0.f;
    #pragma unroll
    for (int q = 0; q < 16; q++) {
        z2 += zr[q].x * zr[q].x;
        z2 += zr[q].y * zr[q].y;
        z2 += zr[q].z * zr[q].z;
        z2 += zr[q].w * zr[q].w;
    }

    float bestd  = 3.402823466e38f;
    float best2d = 3.402823466e38f;
    int   besti  = 0;

    const float4* ef = (const float4*)emb;

    for (int c0 = 0; c0 < NE; c0 += CHUNK) {
        __syncthreads();
        for (int t = threadIdx.x; t < CHUNK * 16; t += K2_THREADS)
            sE[t] = ef[c0 * 16 + t];
        sE2[threadIdx.x] = g_e2[c0 + threadIdx.x];   // K2_THREADS == CHUNK
        __syncthreads();

        #pragma unroll 1
        for (int j = 0; j < CHUNK; j += 4) {
            float d0 = 0.f, d1 = 0.f, d2 = 0.f, d3 = 0.f;
            #pragma unroll
            for (int q = 0; q < 16; q++) {
                float4 a  = zr[q];
                float4 b0 = sE[(j + 0) * 16 + q];
                float4 b1 = sE[(j + 1) * 16 + q];
                float4 b2 = sE[(j + 2) * 16 + q];
                float4 b3 = sE[(j + 3) * 16 + q];
                d0 = fmaf(a.x, b0.x, d0); d0 = fmaf(a.y, b0.y, d0);
                d0 = fmaf(a.z, b0.z, d0); d0 = fmaf(a.w, b0.w, d0);
                d1 = fmaf(a.x, b1.x, d1); d1 = fmaf(a.y, b1.y, d1);
                d1 = fmaf(a.z, b1.z, d1); d1 = fmaf(a.w, b1.w, d1);
                d2 = fmaf(a.x, b2.x, d2); d2 = fmaf(a.y, b2.y, d2);
                d2 = fmaf(a.z, b2.z, d2); d2 = fmaf(a.w, b2.w, d2);
                d3 = fmaf(a.x, b3.x, d3); d3 = fmaf(a.y, b3.y, d3);
                d3 = fmaf(a.z, b3.z, d3); d3 = fmaf(a.w, b3.w, d3);
            }
            float dd0 = (z2 + sE2[j + 0]) - 2.f * d0;
            float dd1 = (z2 + sE2[j + 1]) - 2.f * d1;
            float dd2 = (z2 + sE2[j + 2]) - 2.f * d2;
            float dd3 = (z2 + sE2[j + 3]) - 2.f * d3;
            if (dd0 < bestd) { best2d = bestd; bestd = dd0; besti = c0 + j + 0; }
            else if (dd0 < best2d) best2d = dd0;
            if (dd1 < bestd) { best2d = bestd; bestd = dd1; besti = c0 + j + 1; }
            else if (dd1 < best2d) best2d = dd1;
            if (dd2 < bestd) { best2d = bestd; bestd = dd2; besti = c0 + j + 2; }
            else if (dd2 < best2d) best2d = dd2;
            if (dd3 < bestd) { best2d = bestd; bestd = dd3; besti = c0 + j + 3; }
            else if (dd3 < best2d) best2d = dd3;
        }
    }

    g_idx[row]     = besti;
    idx_out_f[row] = (float)besti;

    if (best2d - bestd < GAP_THRESH) {
        int slot = atomicAdd(&g_flag_cnt, 1);
        g_flag_rows[slot] = row;
    }
}

// ---------------------------------------------------------------------------
// Kernel 2b: refine flagged rows with Kahan-compensated dot products
// (error ~1.5e-9 << reference's own fp32 rounding), same final fp32
// (z2 + e2_j) - 2*dot expression shape, first-min tie-break on index.
// ---------------------------------------------------------------------------
__global__ __launch_bounds__(REFINE_THREADS)
void refine_kernel(const float* __restrict__ z,
                   const float* __restrict__ emb,
                   float* __restrict__ idx_out_f) {
    __shared__ float sz[D];
    __shared__ float sd[REFINE_THREADS];
    __shared__ int   si[REFINE_THREADS];

    int cnt = g_flag_cnt;
    for (int w = blockIdx.x; w < cnt; w += gridDim.x) {
        int row = g_flag_rows[w];

        __syncthreads();
        if (threadIdx.x < D) sz[threadIdx.x] = z[(size_t)row * D + threadIdx.x];
        __syncthreads();

        float z2 = 0.f;
        #pragma unroll
        for (int k = 0; k < D; k++) z2 += sz[k] * sz[k];

        float bestd = 3.402823466e38f;
        int   besti = NE;

        for (int j = threadIdx.x; j < NE; j += REFINE_THREADS) {
            const float* e = emb + (size_t)j * D;
            // Kahan-compensated dot
            float s = 0.f, c = 0.f;
            #pragma unroll
            for (int k = 0; k < D; k++) {
                float p = __fmul_rn(sz[k], e[k]);
                float y = __fadd_rn(p, -c);
                float t = __fadd_rn(s, y);
                c = __fadd_rn(__fadd_rn(t, -s), -y);
                s = t;
            }
            float dot = __fadd_rn(s, c);
            float dd  = __fadd_rn(__fadd_rn(z2, g_e2[j]), -2.f * dot);
            if (dd < bestd || (dd == bestd && j < besti)) { bestd = dd; besti = j; }
        }

        sd[threadIdx.x] = bestd;
        si[threadIdx.x] = besti;
        __syncthreads();
        #pragma unroll
        for (int st = REFINE_THREADS / 2; st > 0; st >>= 1) {
            if (threadIdx.x < st) {
                float od = sd[threadIdx.x + st];
                int   oi = si[threadIdx.x + st];
                if (od < sd[threadIdx.x] ||
                    (od == sd[threadIdx.x] && oi < si[threadIdx.x])) {
                    sd[threadIdx.x] = od;
                    si[threadIdx.x] = oi;
                }
            }
            __syncthreads();
        }
        if (threadIdx.x == 0) {
            g_idx[row]     = si[0];
            idx_out_f[row] = (float)si[0];
        }
    }
}

// ---------------------------------------------------------------------------
// Kernel 3: z_q = embedding[idx], per-block deterministic loss partials.
// zq_out is only 4B-aligned (offset by the 1-float loss) -> scalar stores.
// ---------------------------------------------------------------------------
__global__ __launch_bounds__(K3_THREADS)
void gather_kernel(const float* __restrict__ z,
                   const float* __restrict__ emb,
                   float* __restrict__ zq_out) {
    __shared__ float red[K3_THREADS];
    int row = blockIdx.x * K3_THREADS + threadIdx.x;
    int j   = g_idx[row];

    const float4* ef = (const float4*)(emb + (size_t)j * D);
    const float4* zf = (const float4*)(z + (size_t)row * D);
    float*        o  = zq_out + (size_t)row * D;

    float s = 0.f;
    #pragma unroll
    for (int q = 0; q < 16; q++) {
        float4 e  = ef[q];
        float4 zv = zf[q];
        o[q * 4 + 0] = e.x;
        o[q * 4 + 1] = e.y;
        o[q * 4 + 2] = e.z;
        o[q * 4 + 3] = e.w;
        float dx = e.x - zv.x;
        float dy = e.y - zv.y;
        float dz = e.z - zv.z;
        float dw = e.w - zv.w;
        s += dx * dx; s += dy * dy; s += dz * dz; s += dw * dw;
    }

    red[threadIdx.x] = s;
    __syncthreads();
    #pragma unroll
    for (int st = K3_THREADS / 2; st > 0; st >>= 1) {
        if (threadIdx.x < st) red[threadIdx.x] += red[threadIdx.x + st];
        __syncthreads();
    }
    if (threadIdx.x == 0) g_partial[blockIdx.x] = red[0];
}

// ---------------------------------------------------------------------------
// Kernel 4: final loss reduction. loss = 1.25 * mean((zq - z)^2)
// ---------------------------------------------------------------------------
__global__ void final_kernel(float* __restrict__ out) {
    __shared__ float red[K3_BLOCKS];
    red[threadIdx.x] = g_partial[threadIdx.x];
    __syncthreads();
    #pragma unroll
    for (int st = K3_BLOCKS / 2; st > 0; st >>= 1) {
        if (threadIdx.x < st) red[threadIdx.x] += red[threadIdx.x + st];
        __syncthreads();
    }
    if (threadIdx.x == 0)
        out[0] = 1.25f * red[0] / (float)(N_ROWS * D);
}

// ---------------------------------------------------------------------------
// Launch: out layout = [loss(1) | z_q(N_ROWS*D) | indices(N_ROWS)] fp32
// ---------------------------------------------------------------------------
extern "C" void kernel_launch(void* const* d_in, const int* in_sizes, int n_in,
                              void* d_out, int out_size) {
    const float* z   = (const float*)d_in[0];
    const float* emb = (const float*)d_in[1];
    float* out     = (float*)d_out;
    float* zq_out  = out + 1;
    float* idx_out = out + 1 + (size_t)N_ROWS * D;

    e2_kernel<<<(NE + 255) / 256, 256>>>(emb);
    argmin_kernel<<<N_ROWS / K2_THREADS, K2_THREADS>>>(z, emb, idx_out);
    refine_kernel<<<REFINE_BLOCKS, REFINE_THREADS>>>(z, emb, idx_out);
    gather_kernel<<<K3_BLOCKS, K3_THREADS>>>(z, emb, zq_out);
    final_kernel<<<1, K3_BLOCKS>>>(out);
}

// round 4
// speedup vs baseline: 5.3330x; 5.3330x over previous
#include <cuda_runtime.h>

#define N_ROWS 65536
#define D      64
#define NE     1024
#define CHUNK  128
#define K2_THREADS 128
#define K3_THREADS 256
#define K3_BLOCKS  1024                  // 4 threads per row
#define GAP_THRESH 1e-4f
#define REFINE_BLOCKS 256
#define REFINE_THREADS 128

// Scratch (no allocations allowed)
__device__ float g_e2[NE];
__device__ int   g_idx[N_ROWS];
__device__ float g_partial[K3_BLOCKS];
__device__ int   g_flag_cnt;
__device__ int   g_flag_rows[N_ROWS];

// ---------------------------------------------------------------------------
// Packed f32x2 helpers (sm_103a): one instruction = two IEEE fp32 FMAs.
// ---------------------------------------------------------------------------
__device__ __forceinline__ unsigned long long pack_f2(float lo, float hi) {
    unsigned long long r;
    asm("mov.b64 %0, {%1, %2};" : "=l"(r) : "f"(lo), "f"(hi));
    return r;
}
__device__ __forceinline__ unsigned long long fma_f32x2(
    unsigned long long a, unsigned long long b, unsigned long long c) {
    unsigned long long d;
    asm("fma.rn.f32x2 %0, %1, %2, %3;" : "=l"(d) : "l"(a), "l"(b), "l"(c));
    return d;
}
__device__ __forceinline__ float hsum_f2(unsigned long long v) {
    float lo, hi;
    asm("mov.b64 {%0, %1}, %2;" : "=f"(lo), "=f"(hi) : "l"(v));
    return lo + hi;
}

// ---------------------------------------------------------------------------
// Kernel 1: e2[j] = sum_d emb[j,d]^2   (+ reset flag counter)
// ---------------------------------------------------------------------------
__global__ void e2_kernel(const float* __restrict__ emb) {
    int j = blockIdx.x * blockDim.x + threadIdx.x;
    if (j == 0) g_flag_cnt = 0;
    if (j < NE) {
        const float4* e = (const float4*)(emb + (size_t)j * D);
        float s = 0.f;
        #pragma unroll
        for (int q = 0; q < 16; q++) {
            float4 v = e[q];
            s += v.x * v.x;
            s += v.y * v.y;
            s += v.z * v.z;
            s += v.w * v.w;
        }
        g_e2[j] = s;
    }
}

// ---------------------------------------------------------------------------
// Kernel 2: fast fp32 argmin, packed f32x2 math.
// 1 row/thread; codes streamed through shared in chunks of 128; 4-code
// register blocking; each f32x2 FMA covers two adjacent dims (even/odd
// partial sums in one packed accumulator, horizontal add at the end).
// Tracks best + second-best; near-ties (gap < GAP_THRESH) -> refine list.
// ---------------------------------------------------------------------------
__global__ __launch_bounds__(K2_THREADS)
void argmin_kernel(const float* __restrict__ z,
                   const float* __restrict__ emb,
                   float* __restrict__ idx_out_f) {
    __shared__ float4 sE[CHUNK * 16];
    __shared__ float  sE2[CHUNK];

    int row = blockIdx.x * K2_THREADS + threadIdx.x;

    // z row: 32 packed dim-pairs
    unsigned long long zu[32];
    float z2 = 0.f;
    {
        const float4* zp = (const float4*)(z + (size_t)row * D);
        #pragma unroll
        for (int q = 0; q < 16; q++) {
            float4 v = zp[q];
            zu[2 * q + 0] = pack_f2(v.x, v.y);
            zu[2 * q + 1] = pack_f2(v.z, v.w);
            z2 += v.x * v.x;
            z2 += v.y * v.y;
            z2 += v.z * v.z;
            z2 += v.w * v.w;
        }
    }

    float bestd  = 3.402823466e38f;
    float best2d = 3.402823466e38f;
    int   besti  = 0;

    const float4* ef = (const float4*)emb;

    for (int c0 = 0; c0 < NE; c0 += CHUNK) {
        __syncthreads();
        for (int t = threadIdx.x; t < CHUNK * 16; t += K2_THREADS)
            sE[t] = ef[c0 * 16 + t];
        sE2[threadIdx.x] = g_e2[c0 + threadIdx.x];   // K2_THREADS == CHUNK
        __syncthreads();

        #pragma unroll 1
        for (int j = 0; j < CHUNK; j += 4) {
            unsigned long long a0 = 0ull, a1 = 0ull, a2 = 0ull, a3 = 0ull;
            #pragma unroll
            for (int q = 0; q < 16; q++) {
                float4 b0 = sE[(j + 0) * 16 + q];
                float4 b1 = sE[(j + 1) * 16 + q];
                float4 b2 = sE[(j + 2) * 16 + q];
                float4 b3 = sE[(j + 3) * 16 + q];
                unsigned long long ze = zu[2 * q + 0];
                unsigned long long zo = zu[2 * q + 1];
                a0 = fma_f32x2(ze, pack_f2(b0.x, b0.y), a0);
                a0 = fma_f32x2(zo, pack_f2(b0.z, b0.w), a0);
                a1 = fma_f32x2(ze, pack_f2(b1.x, b1.y), a1);
                a1 = fma_f32x2(zo, pack_f2(b1.z, b1.w), a1);
                a2 = fma_f32x2(ze, pack_f2(b2.x, b2.y), a2);
                a2 = fma_f32x2(zo, pack_f2(b2.z, b2.w), a2);
                a3 = fma_f32x2(ze, pack_f2(b3.x, b3.y), a3);
                a3 = fma_f32x2(zo, pack_f2(b3.z, b3.w), a3);
            }
            float dd0 = (z2 + sE2[j + 0]) - 2.f * hsum_f2(a0);
            float dd1 = (z2 + sE2[j + 1]) - 2.f * hsum_f2(a1);
            float dd2 = (z2 + sE2[j + 2]) - 2.f * hsum_f2(a2);
            float dd3 = (z2 + sE2[j + 3]) - 2.f * hsum_f2(a3);
            if (dd0 < bestd) { best2d = bestd; bestd = dd0; besti = c0 + j + 0; }
            else if (dd0 < best2d) best2d = dd0;
            if (dd1 < bestd) { best2d = bestd; bestd = dd1; besti = c0 + j + 1; }
            else if (dd1 < best2d) best2d = dd1;
            if (dd2 < bestd) { best2d = bestd; bestd = dd2; besti = c0 + j + 2; }
            else if (dd2 < best2d) best2d = dd2;
            if (dd3 < bestd) { best2d = bestd; bestd = dd3; besti = c0 + j + 3; }
            else if (dd3 < best2d) best2d = dd3;
        }
    }

    g_idx[row]     = besti;
    idx_out_f[row] = (float)besti;

    if (best2d - bestd < GAP_THRESH) {
        int slot = atomicAdd(&g_flag_cnt, 1);
        g_flag_rows[slot] = row;
    }
}

// ---------------------------------------------------------------------------
// Kernel 2b: refine flagged rows with Kahan-compensated dots (error ~1e-9,
// far below the reference's own fp32 rounding). float4 loads for MLP;
// first-min tie-break on index.
// ---------------------------------------------------------------------------
__global__ __launch_bounds__(REFINE_THREADS)
void refine_kernel(const float* __restrict__ z,
                   const float* __restrict__ emb,
                   float* __restrict__ idx_out_f) {
    __shared__ float sz[D];
    __shared__ float sd[REFINE_THREADS];
    __shared__ int   si[REFINE_THREADS];

    int cnt = g_flag_cnt;
    for (int w = blockIdx.x; w < cnt; w += gridDim.x) {
        int row = g_flag_rows[w];

        __syncthreads();
        if (threadIdx.x < D) sz[threadIdx.x] = z[(size_t)row * D + threadIdx.x];
        __syncthreads();

        float z2 = 0.f;
        #pragma unroll
        for (int k = 0; k < D; k++) z2 += sz[k] * sz[k];

        float bestd = 3.402823466e38f;
        int   besti = NE;

        for (int j = threadIdx.x; j < NE; j += REFINE_THREADS) {
            const float4* e = (const float4*)(emb + (size_t)j * D);
            float4 ev[16];
            #pragma unroll
            for (int q = 0; q < 16; q++) ev[q] = e[q];   // batched LDG.128

            float s = 0.f, c = 0.f;
            #pragma unroll
            for (int q = 0; q < 16; q++) {
                float el[4] = {ev[q].x, ev[q].y, ev[q].z, ev[q].w};
                #pragma unroll
                for (int u = 0; u < 4; u++) {
                    float p = __fmul_rn(sz[q * 4 + u], el[u]);
                    float y = __fadd_rn(p, -c);
                    float t = __fadd_rn(s, y);
                    c = __fadd_rn(__fadd_rn(t, -s), -y);
                    s = t;
                }
            }
            float dot = __fadd_rn(s, c);
            float dd  = __fadd_rn(__fadd_rn(z2, g_e2[j]), -2.f * dot);
            if (dd < bestd || (dd == bestd && j < besti)) { bestd = dd; besti = j; }
        }

        sd[threadIdx.x] = bestd;
        si[threadIdx.x] = besti;
        __syncthreads();
        #pragma unroll
        for (int st = REFINE_THREADS / 2; st > 0; st >>= 1) {
            if (threadIdx.x < st) {
                float od = sd[threadIdx.x + st];
                int   oi = si[threadIdx.x + st];
                if (od < sd[threadIdx.x] ||
                    (od == sd[threadIdx.x] && oi < si[threadIdx.x])) {
                    sd[threadIdx.x] = od;
                    si[threadIdx.x] = oi;
                }
            }
            __syncthreads();
        }
        if (threadIdx.x == 0) {
            g_idx[row]     = si[0];
            idx_out_f[row] = (float)si[0];
        }
    }
}

// ---------------------------------------------------------------------------
// Kernel 3: z_q gather + loss partials. 4 threads per row (16 floats each)
// for latency hiding. Output emulates the straight-through expression
// out = z + (z_q - z) in fp32, bit-matching the reference.
// zq_out is only 4B-aligned -> scalar stores.
// ---------------------------------------------------------------------------
__global__ __launch_bounds__(K3_THREADS)
void gather_kernel(const float* __restrict__ z,
                   const float* __restrict__ emb,
                   float* __restrict__ zq_out) {
    __shared__ float red[K3_THREADS];
    int gt   = blockIdx.x * K3_THREADS + threadIdx.x;
    int row  = gt >> 2;
    int part = gt & 3;
    int j    = g_idx[row];

    const float4* ef = (const float4*)(emb + (size_t)j * D + part * 16);
    const float4* zf = (const float4*)(z + (size_t)row * D + part * 16);
    float*        o  = zq_out + (size_t)row * D + part * 16;

    float s = 0.f;
    #pragma unroll
    for (int q = 0; q < 4; q++) {
        float4 e  = ef[q];
        float4 zv = zf[q];
        float dx = __fadd_rn(e.x, -zv.x);
        float dy = __fadd_rn(e.y, -zv.y);
        float dz = __fadd_rn(e.z, -zv.z);
        float dw = __fadd_rn(e.w, -zv.w);
        o[q * 4 + 0] = __fadd_rn(zv.x, dx);
        o[q * 4 + 1] = __fadd_rn(zv.y, dy);
        o[q * 4 + 2] = __fadd_rn(zv.z, dz);
        o[q * 4 + 3] = __fadd_rn(zv.w, dw);
        s += dx * dx; s += dy * dy; s += dz * dz; s += dw * dw;
    }

    red[threadIdx.x] = s;
    __syncthreads();
    #pragma unroll
    for (int st = K3_THREADS / 2; st > 0; st >>= 1) {
        if (threadIdx.x < st) red[threadIdx.x] += red[threadIdx.x + st];
        __syncthreads();
    }
    if (threadIdx.x == 0) g_partial[blockIdx.x] = red[0];
}

// ---------------------------------------------------------------------------
// Kernel 4: final loss reduction over 1024 partials.
// loss = 1.25 * mean((zq - z)^2)
// ---------------------------------------------------------------------------
__global__ void final_kernel(float* __restrict__ out) {
    __shared__ float red[256];
    float s = 0.f;
    #pragma unroll
    for (int q = 0; q < 4; q++) s += g_partial[threadIdx.x + 256 * q];
    red[threadIdx.x] = s;
    __syncthreads();
    #pragma unroll
    for (int st = 128; st > 0; st >>= 1) {
        if (threadIdx.x < st) red[threadIdx.x] += red[threadIdx.x + st];
        __syncthreads();
    }
    if (threadIdx.x == 0)
        out[0] = 1.25f * red[0] / (float)(N_ROWS * D);
}

// ---------------------------------------------------------------------------
// Launch: out layout = [loss(1) | z_q(N_ROWS*D) | indices(N_ROWS)] fp32
// ---------------------------------------------------------------------------
extern "C" void kernel_launch(void* const* d_in, const int* in_sizes, int n_in,
                              void* d_out, int out_size) {
    const float* z   = (const float*)d_in[0];
    const float* emb = (const float*)d_in[1];
    float* out     = (float*)d_out;
    float* zq_out  = out + 1;
    float* idx_out = out + 1 + (size_t)N_ROWS * D;

    e2_kernel<<<(NE + 255) / 256, 256>>>(emb);
    argmin_kernel<<<N_ROWS / K2_THREADS, K2_THREADS>>>(z, emb, idx_out);
    refine_kernel<<<REFINE_BLOCKS, REFINE_THREADS>>>(z, emb, idx_out);
    gather_kernel<<<K3_BLOCKS, K3_THREADS>>>(z, emb, zq_out);
    final_kernel<<<1, 256>>>(out);
}